// round 15
// baseline (speedup 1.0000x reference)
#include <cuda_runtime.h>
#include <cstdint>

#define BB 256
#define LL 512
#define DD 64
#define NSPLIT 4
#define NBLK (BB * NSPLIT)        // 1024 blocks
#define RPB 128                   // rows per block (quarter batch)
#define EPS_LOG 1e-7f
#define EPS_COS 1e-8f

__device__ float g_m[NBLK];
__device__ float g_pos[NBLK];
__device__ float g_neg[NBLK];
__device__ int   g_cnt = 0;

__global__ __launch_bounds__(256)
void wnl_fused(const float* __restrict__ emb,
               const float* __restrict__ probs,
               const float* __restrict__ labels,
               float* __restrict__ out)
{
    const int bid  = blockIdx.x;       // 0..1023
    const int b    = bid >> 2;         // batch 0..255
    const int qtr  = bid & 3;          // quarter 0..3
    const int tid  = threadIdx.x;      // 0..255
    const int wid  = tid >> 5;         // 0..7
    const int lane = tid & 31;
    const int g    = lane >> 3;        // 4 row-groups per warp
    const int s    = lane & 7;         // 8 lanes per row

    __shared__ float s_m[8], s_pos[8], s_neg[8], s_sum[8];
    __shared__ int   s_last;

    const float* __restrict__ embB = emb    + (size_t)b * LL * DD;
    const float* __restrict__ labB = labels + (size_t)b * LL;
    const float* __restrict__ prbB = probs  + (size_t)b * LL;

    if (tid == 0) s_last = 0;

    const int rowBase = qtr * RPB + wid * 16;  // warp covers 16 rows

    // ---- issue ALL control loads at cycle 0 (independent of each other) ----
    const float labdiag = __ldg(&labB[b]);               // gate for whole batch
    const float lv      = labB[rowBase + (lane & 15)];   // 16 row labels / warp
    float pr = 0.f, myl = 0.f;
    if (tid < RPB) {                                     // this quarter's probs
        pr  = prbB[qtr * RPB + tid];
        myl = labB[qtr * RPB + tid];
    }
    // query row per lane (tiny: 256B/block; always load, no dependency)
    const float4 qa = *(const float4*)(embB + (size_t)b * DD + s * 4);
    const float4 qb = *(const float4*)(embB + (size_t)b * DD + 32 + s * 4);

    float m = 0.f;
    if (labdiag == 0.f) {                      // dead batches skip all emb reads
        float nq2 = qa.x*qa.x + qa.y*qa.y + qa.z*qa.z + qa.w*qa.w
                  + qb.x*qb.x + qb.y*qb.y + qb.z*qb.z + qb.w*qb.w;
        #pragma unroll
        for (int o = 4; o; o >>= 1) nq2 += __shfl_xor_sync(0xffffffffu, nq2, o);
        const float nq = sqrtf(nq2);

        #pragma unroll
        for (int it = 0; it < 4; it++) {
            const int   k   = rowBase + it * 4 + g;
            const float lab = __shfl_sync(0xffffffffu, lv, it * 4 + g);
            // BRANCHLESS predicated load: dead rows re-read the (L1-resident)
            // query row -> no BSSY, loads batch freely, ~zero extra DRAM.
            // Garbage result erased exactly by *lab below.
            const size_t roff = (lab != 0.f) ? (size_t)k * DD : (size_t)b * DD;
            const float* rp = embB + roff;
            const float4 xa = *(const float4*)(rp + s * 4);
            const float4 xb = *(const float4*)(rp + 32 + s * 4);
            float d = qa.x*xa.x + qa.y*xa.y + qa.z*xa.z + qa.w*xa.w
                    + qb.x*xb.x + qb.y*xb.y + qb.z*xb.z + qb.w*xb.w;
            float n = xa.x*xa.x + xa.y*xa.y + xa.z*xa.z + xa.w*xa.w
                    + xb.x*xb.x + xb.y*xb.y + xb.z*xb.z + xb.w*xb.w;
            #pragma unroll
            for (int o = 4; o; o >>= 1) {
                d += __shfl_xor_sync(0xffffffffu, d, o);
                n += __shfl_xor_sync(0xffffffffu, n, o);
            }
            const float cosv = __fdividef(d, fmaxf(nq * sqrtf(n), EPS_COS));
            m = fmaxf(m, fmaxf(cosv, 0.f) * lab);   // lab==0 -> exact 0
        }
    }

    // ---- log terms (fast-math logs; err ~1e-6 << 1e-3 tolerance) ----
    float pos = 0.f, neg = 0.f;
    if (tid < RPB) {
        const float pe = pr + EPS_LOG;
        pos = myl * __logf(pe);
        neg = __logf(1.0f - pe);
    }

    // ---- warp combine: max(m), sum(pos), sum(neg) ----
    #pragma unroll
    for (int o = 16; o; o >>= 1) {
        m    = fmaxf(m, __shfl_xor_sync(0xffffffffu, m, o));
        pos += __shfl_xor_sync(0xffffffffu, pos, o);
        neg += __shfl_xor_sync(0xffffffffu, neg, o);
    }
    if (lane == 0) { s_m[wid] = m; s_pos[wid] = pos; s_neg[wid] = neg; }
    __syncthreads();

    if (wid == 0) {
        float mm = (lane < 8) ? s_m[lane]   : 0.f;
        float pp = (lane < 8) ? s_pos[lane] : 0.f;
        float nn = (lane < 8) ? s_neg[lane] : 0.f;
        #pragma unroll
        for (int o = 4; o; o >>= 1) {
            mm = fmaxf(mm, __shfl_xor_sync(0xffffffffu, mm, o));
            pp += __shfl_xor_sync(0xffffffffu, pp, o);
            nn += __shfl_xor_sync(0xffffffffu, nn, o);
        }
        if (lane == 0) {
            g_m[bid] = mm; g_pos[bid] = pp; g_neg[bid] = nn;
            __threadfence();
            const int old = atomicAdd(&g_cnt, 1);
            if (old == NBLK - 1) s_last = 1;   // this block finishes the job
        }
    }
    __syncthreads();

    // ---- last-block final combine (deterministic fixed-order) ----
    if (s_last) {
        __threadfence();
        const int b2 = tid;                    // one batch per thread
        float mm = __ldcg(&g_m[4*b2]);
        float pp = __ldcg(&g_pos[4*b2]);
        float nn = __ldcg(&g_neg[4*b2]);
        #pragma unroll
        for (int j = 1; j < NSPLIT; j++) {
            mm = fmaxf(mm, __ldcg(&g_m[4*b2 + j]));
            pp += __ldcg(&g_pos[4*b2 + j]);
            nn += __ldcg(&g_neg[4*b2 + j]);
        }
        const float ld2 = __ldg(&labels[(size_t)b2 * LL + b2]);
        const float wnl = (ld2 == 0.f) ? mm : 0.f;
        float contrib = -pp - wnl * nn;

        #pragma unroll
        for (int o = 16; o; o >>= 1)
            contrib += __shfl_xor_sync(0xffffffffu, contrib, o);
        if (lane == 0) s_sum[wid] = contrib;
        __syncthreads();
        if (wid == 0) {
            float t = (lane < 8) ? s_sum[lane] : 0.f;
            #pragma unroll
            for (int o = 4; o; o >>= 1) t += __shfl_xor_sync(0xffffffffu, t, o);
            if (lane == 0) {
                out[0] = t / (float)BB;
                g_cnt = 0;                     // reset for next graph replay
            }
        }
    }
}

extern "C" void kernel_launch(void* const* d_in, const int* in_sizes, int n_in,
                              void* d_out, int out_size)
{
    const float* emb    = (const float*)d_in[0]; // (256, 512, 64) f32
    const float* probs  = (const float*)d_in[1]; // (256, 512) f32
    const float* labels = (const float*)d_in[2]; // (256, 512) f32
    float* out = (float*)d_out;                  // scalar f32

    wnl_fused<<<NBLK, 256>>>(emb, probs, labels, out);
}

// round 16
// speedup vs baseline: 1.0158x; 1.0158x over previous
#include <cuda_runtime.h>
#include <cstdint>

#define BB 256
#define LL 512
#define DD 64
#define EPS_LOG 1e-7f
#define EPS_COS 1e-8f

__device__ float g_part[BB];      // finished per-batch contribution
__device__ int   g_cnt = 0;

__global__ __launch_bounds__(512)
void wnl_fused(const float* __restrict__ emb,
               const float* __restrict__ probs,
               const float* __restrict__ labels,
               float* __restrict__ out)
{
    const int b    = blockIdx.x;       // batch 0..255, one block per batch
    const int tid  = threadIdx.x;      // 0..511
    const int wid  = tid >> 5;         // 0..15
    const int lane = tid & 31;
    const int g    = lane >> 3;        // 4 row-groups per warp
    const int s    = lane & 7;         // 8 lanes per row

    __shared__ float s_m[16], s_pos[16], s_neg[16], s_sum[16];
    __shared__ int   s_last;

    const float* __restrict__ embB = emb    + (size_t)b * LL * DD;
    const float* __restrict__ labB = labels + (size_t)b * LL;
    const float* __restrict__ prbB = probs  + (size_t)b * LL;

    if (tid == 0) s_last = 0;

    const int rowBase = wid * 32;      // warp covers 32 rows of this batch

    // ---- issue ALL control loads at cycle 0 (independent of each other) ----
    const float labdiag = __ldg(&labB[b]);            // gate for whole batch
    const float lv      = labB[rowBase + lane];       // 32 row labels / warp
    const float pr      = prbB[tid];                  // prob for log terms
    const float myl     = labB[tid];                  // label for pos term
    // query row per lane (256B, loaded once per batch now)
    const float4 qa = *(const float4*)(embB + (size_t)b * DD + s * 4);
    const float4 qb = *(const float4*)(embB + (size_t)b * DD + 32 + s * 4);

    float m = 0.f;
    if (labdiag == 0.f) {              // dead batches skip all emb reads
        float nq2 = qa.x*qa.x + qa.y*qa.y + qa.z*qa.z + qa.w*qa.w
                  + qb.x*qb.x + qb.y*qb.y + qb.z*qb.z + qb.w*qb.w;
        #pragma unroll
        for (int o = 4; o; o >>= 1) nq2 += __shfl_xor_sync(0xffffffffu, nq2, o);
        const float nq = sqrtf(nq2);

        #pragma unroll
        for (int it = 0; it < 8; it++) {
            const int   k   = rowBase + it * 4 + g;
            const float lab = __shfl_sync(0xffffffffu, lv, it * 4 + g);
            // BRANCHLESS predicated load: dead rows re-read the (L1-resident)
            // query row -> no BSSY, loads batch freely, ~zero extra DRAM.
            // Garbage result is erased exactly by *lab below.
            const size_t roff = (lab != 0.f) ? (size_t)k * DD : (size_t)b * DD;
            const float* rp = embB + roff;
            const float4 xa = *(const float4*)(rp + s * 4);
            const float4 xb = *(const float4*)(rp + 32 + s * 4);
            float d = qa.x*xa.x + qa.y*xa.y + qa.z*xa.z + qa.w*xa.w
                    + qb.x*xb.x + qb.y*xb.y + qb.z*xb.z + qb.w*xb.w;
            float n = xa.x*xa.x + xa.y*xa.y + xa.z*xa.z + xa.w*xa.w
                    + xb.x*xb.x + xb.y*xb.y + xb.z*xb.z + xb.w*xb.w;
            #pragma unroll
            for (int o = 4; o; o >>= 1) {
                d += __shfl_xor_sync(0xffffffffu, d, o);
                n += __shfl_xor_sync(0xffffffffu, n, o);
            }
            const float cosv = __fdividef(d, fmaxf(nq * sqrtf(n), EPS_COS));
            m = fmaxf(m, fmaxf(cosv, 0.f) * lab);    // lab==0 -> exact 0
        }
    }

    // ---- log terms (fast-math logs; err ~1e-6 << 1e-3 tolerance) ----
    const float pe  = pr + EPS_LOG;
    float pos = myl * __logf(pe);
    float neg = __logf(1.0f - pe);

    // ---- warp combine: max(m), sum(pos), sum(neg) ----
    #pragma unroll
    for (int o = 16; o; o >>= 1) {
        m    = fmaxf(m, __shfl_xor_sync(0xffffffffu, m, o));
        pos += __shfl_xor_sync(0xffffffffu, pos, o);
        neg += __shfl_xor_sync(0xffffffffu, neg, o);
    }
    if (lane == 0) { s_m[wid] = m; s_pos[wid] = pos; s_neg[wid] = neg; }
    __syncthreads();

    if (wid == 0) {
        float mm = (lane < 16) ? s_m[lane]   : 0.f;
        float pp = (lane < 16) ? s_pos[lane] : 0.f;
        float nn = (lane < 16) ? s_neg[lane] : 0.f;
        #pragma unroll
        for (int o = 8; o; o >>= 1) {
            mm = fmaxf(mm, __shfl_xor_sync(0xffffffffu, mm, o));
            pp += __shfl_xor_sync(0xffffffffu, pp, o);
            nn += __shfl_xor_sync(0xffffffffu, nn, o);
        }
        if (lane == 0) {
            // finished per-batch contribution (labdiag applied here)
            const float wnl = (labdiag == 0.f) ? mm : 0.f;
            g_part[b] = -pp - wnl * nn;
            __threadfence();
            const int old = atomicAdd(&g_cnt, 1);
            if (old == BB - 1) s_last = 1;     // this block finishes the job
        }
    }
    __syncthreads();

    // ---- last block: flat deterministic sum of 256 contributions ----
    if (s_last) {
        __threadfence();
        float v = (tid < BB) ? __ldcg(&g_part[tid]) : 0.f;
        #pragma unroll
        for (int o = 16; o; o >>= 1) v += __shfl_xor_sync(0xffffffffu, v, o);
        if (lane == 0) s_sum[wid] = v;
        __syncthreads();
        if (wid == 0) {
            float t = (lane < 16) ? s_sum[lane] : 0.f;
            #pragma unroll
            for (int o = 8; o; o >>= 1) t += __shfl_xor_sync(0xffffffffu, t, o);
            if (lane == 0) {
                out[0] = t / (float)BB;
                g_cnt = 0;                     // reset for next graph replay
            }
        }
    }
}

extern "C" void kernel_launch(void* const* d_in, const int* in_sizes, int n_in,
                              void* d_out, int out_size)
{
    const float* emb    = (const float*)d_in[0]; // (256, 512, 64) f32
    const float* probs  = (const float*)d_in[1]; // (256, 512) f32
    const float* labels = (const float*)d_in[2]; // (256, 512) f32
    float* out = (float*)d_out;                  // scalar f32

    wnl_fused<<<BB, 512>>>(emb, probs, labels, out);
}

// round 17
// speedup vs baseline: 1.1488x; 1.1310x over previous
#include <cuda_runtime.h>
#include <cstdint>

#define BB 256
#define LL 512
#define DD 64
#define NSPLIT 2
#define NBLK (BB * NSPLIT)        // 512 blocks -- proven optimal shape
#define EPS_LOG 1e-7f
#define EPS_COS 1e-8f

__device__ float g_m[NBLK];
__device__ float g_pos[NBLK];
__device__ float g_neg[NBLK];
__device__ int   g_cnt = 0;

__global__ __launch_bounds__(256)
void wnl_fused(const float* __restrict__ emb,
               const float* __restrict__ probs,
               const float* __restrict__ labels,
               float* __restrict__ out)
{
    const int bid  = blockIdx.x;       // 0..511
    const int b    = bid >> 1;         // batch 0..255
    const int h    = bid & 1;          // half 0/1
    const int tid  = threadIdx.x;      // 0..255
    const int wid  = tid >> 5;         // 0..7
    const int lane = tid & 31;
    const int g    = lane >> 2;        // 8 row-groups per warp
    const int s    = lane & 3;         // 4 lanes per row (16 floats each)

    __shared__ float s_m[8], s_pos[8], s_neg[8], s_sum[8];
    __shared__ int   s_last;

    const float* __restrict__ embB = emb    + (size_t)b * LL * DD;
    const float* __restrict__ labB = labels + (size_t)b * LL;
    const float* __restrict__ prbB = probs  + (size_t)b * LL;

    if (tid == 0) s_last = 0;

    const int rowBase = h * 256 + wid * 32;    // warp covers 32 rows

    // ---- issue ALL control loads at cycle 0 (independent) ----
    const float labdiag = __ldg(&labB[b]);               // gate for whole batch
    const float lv      = labB[rowBase + lane];          // 32 row labels / warp
    const float pr      = prbB[h * 256 + tid];           // prob for log terms
    const float myl     = labB[h * 256 + tid];           // label for pos term
    // query: lane owns 16 contiguous floats [s*16, s*16+16)
    const float* qp = embB + (size_t)b * DD + s * 16;
    const float4 q0 = *(const float4*)(qp +  0);
    const float4 q1 = *(const float4*)(qp +  4);
    const float4 q2 = *(const float4*)(qp +  8);
    const float4 q3 = *(const float4*)(qp + 12);

    // ||q||^2 over 4 lanes (unconditional; cheap, feeds final scale)
    float nq2 = q0.x*q0.x + q0.y*q0.y + q0.z*q0.z + q0.w*q0.w
              + q1.x*q1.x + q1.y*q1.y + q1.z*q1.z + q1.w*q1.w
              + q2.x*q2.x + q2.y*q2.y + q2.z*q2.z + q2.w*q2.w
              + q3.x*q3.x + q3.y*q3.y + q3.z*q3.z + q3.w*q3.w;
    nq2 += __shfl_xor_sync(0xffffffffu, nq2, 2);
    nq2 += __shfl_xor_sync(0xffffffffu, nq2, 1);

    float m = 0.f;                     // unscaled masked row-max (>=0 => relu free)
    if (labdiag == 0.f) {              // dead batches skip all emb reads
        // hoist all label broadcasts -> loads below batch back-to-back
        float labv[4];
        #pragma unroll
        for (int it = 0; it < 4; it++)
            labv[it] = __shfl_sync(0xffffffffu, lv, it * 8 + g);

        #pragma unroll
        for (int it = 0; it < 4; it++) {
            const int   k   = rowBase + it * 8 + g;
            const float lab = labv[it];
            // branchless predicated load: dead rows re-read (L1-resident) query
            const size_t roff = (lab != 0.f) ? (size_t)k * DD : (size_t)b * DD;
            const float* rp = embB + roff + s * 16;
            const float4 x0 = *(const float4*)(rp +  0);
            const float4 x1 = *(const float4*)(rp +  4);
            const float4 x2 = *(const float4*)(rp +  8);
            const float4 x3 = *(const float4*)(rp + 12);
            float d = q0.x*x0.x + q0.y*x0.y + q0.z*x0.z + q0.w*x0.w
                    + q1.x*x1.x + q1.y*x1.y + q1.z*x1.z + q1.w*x1.w
                    + q2.x*x2.x + q2.y*x2.y + q2.z*x2.z + q2.w*x2.w
                    + q3.x*x3.x + q3.y*x3.y + q3.z*x3.z + q3.w*x3.w;
            float n = x0.x*x0.x + x0.y*x0.y + x0.z*x0.z + x0.w*x0.w
                    + x1.x*x1.x + x1.y*x1.y + x1.z*x1.z + x1.w*x1.w
                    + x2.x*x2.x + x2.y*x2.y + x2.z*x2.z + x2.w*x2.w
                    + x3.x*x3.x + x3.y*x3.y + x3.z*x3.z + x3.w*x3.w;
            d += __shfl_xor_sync(0xffffffffu, d, 2);
            n += __shfl_xor_sync(0xffffffffu, n, 2);
            d += __shfl_xor_sync(0xffffffffu, d, 1);
            n += __shfl_xor_sync(0xffffffffu, n, 1);
            // m = max(m, relu(cos)*lab) * ||q||  -- ||q|| scale deferred;
            // max-vs-0 = relu; lab==0 zeroes garbage rows exactly
            m = fmaxf(m, d * rsqrtf(n) * lab);
        }
    }

    // ---- log terms (fast-math; err ~1e-6 << 1e-3 tol) ----
    const float pe  = pr + EPS_LOG;
    float pos = myl * __logf(pe);
    float neg = __logf(1.0f - pe);

    // ---- warp combine: max(m), sum(pos), sum(neg) ----
    #pragma unroll
    for (int o = 16; o; o >>= 1) {
        m    = fmaxf(m, __shfl_xor_sync(0xffffffffu, m, o));
        pos += __shfl_xor_sync(0xffffffffu, pos, o);
        neg += __shfl_xor_sync(0xffffffffu, neg, o);
    }
    if (lane == 0) { s_m[wid] = m; s_pos[wid] = pos; s_neg[wid] = neg; }
    __syncthreads();

    if (wid == 0) {
        float mm = (lane < 8) ? s_m[lane]   : 0.f;
        float pp = (lane < 8) ? s_pos[lane] : 0.f;
        float nn = (lane < 8) ? s_neg[lane] : 0.f;
        #pragma unroll
        for (int o = 4; o; o >>= 1) {
            mm = fmaxf(mm, __shfl_xor_sync(0xffffffffu, mm, o));
            pp += __shfl_xor_sync(0xffffffffu, pp, o);
            nn += __shfl_xor_sync(0xffffffffu, nn, o);
        }
        if (lane == 0) {
            // apply the deferred 1/||q|| scale exactly once (positive, order-safe)
            g_m[bid] = mm * rsqrtf(nq2);
            g_pos[bid] = pp; g_neg[bid] = nn;
            __threadfence();
            const int old = atomicAdd(&g_cnt, 1);
            if (old == NBLK - 1) s_last = 1;   // this block finishes the job
        }
    }
    __syncthreads();

    // ---- last-block final combine (deterministic fixed-order) ----
    if (s_last) {
        __threadfence();
        const int b2 = tid;                    // one batch per thread
        float mm = fmaxf(__ldcg(&g_m[2*b2]),  __ldcg(&g_m[2*b2+1]));
        float pp = __ldcg(&g_pos[2*b2]) + __ldcg(&g_pos[2*b2+1]);
        float nn = __ldcg(&g_neg[2*b2]) + __ldcg(&g_neg[2*b2+1]);
        const float ld2 = __ldg(&labels[(size_t)b2 * LL + b2]);
        const float wnl = (ld2 == 0.f) ? mm : 0.f;
        float contrib = -pp - wnl * nn;

        #pragma unroll
        for (int o = 16; o; o >>= 1)
            contrib += __shfl_xor_sync(0xffffffffu, contrib, o);
        if (lane == 0) s_sum[wid] = contrib;
        __syncthreads();
        if (wid == 0) {
            float t = (lane < 8) ? s_sum[lane] : 0.f;
            #pragma unroll
            for (int o = 4; o; o >>= 1) t += __shfl_xor_sync(0xffffffffu, t, o);
            if (lane == 0) {
                out[0] = t / (float)BB;
                g_cnt = 0;                     // reset for next graph replay
            }
        }
    }
}

extern "C" void kernel_launch(void* const* d_in, const int* in_sizes, int n_in,
                              void* d_out, int out_size)
{
    const float* emb    = (const float*)d_in[0]; // (256, 512, 64) f32
    const float* probs  = (const float*)d_in[1]; // (256, 512) f32
    const float* labels = (const float*)d_in[2]; // (256, 512) f32
    float* out = (float*)d_out;                  // scalar f32

    wnl_fused<<<NBLK, 256>>>(emb, probs, labels, out);
}